// round 4
// baseline (speedup 1.0000x reference)
#include <cuda_runtime.h>
#include <cstdint>

#define BB    4
#define SS    2048
#define DD    1024
#define HH    16
#define DEPTH 64
#define MTOT  (BB * SS)

__device__ float g_q  [(size_t)BB * HH * SS * DEPTH];
__device__ float g_k  [(size_t)BB * HH * SS * DEPTH];
__device__ float g_v  [(size_t)BB * HH * SS * DEPTH];
__device__ float g_ctx[(size_t)BB * SS * DD];
__device__ float g_attn_fb[(size_t)BB * HH * SS * SS];

// ---------------------------------------------------------------------------
__device__ __forceinline__ uint32_t f2tf(float x) {
    uint32_t r;
    asm("cvt.rna.tf32.f32 %0, %1;" : "=r"(r) : "f"(x));
    return r;
}

__device__ __forceinline__ void mma_tf32(float* c, const uint32_t* a, const uint32_t* b) {
    asm volatile(
        "mma.sync.aligned.m16n8k8.row.col.f32.tf32.tf32.f32 "
        "{%0,%1,%2,%3}, {%4,%5,%6,%7}, {%8,%9}, {%0,%1,%2,%3};"
        : "+f"(c[0]), "+f"(c[1]), "+f"(c[2]), "+f"(c[3])
        : "r"(a[0]), "r"(a[1]), "r"(a[2]), "r"(a[3]), "r"(b[0]), "r"(b[1]));
}

// Swizzled tile: [kt8][lane][reg] — one LDS.128 per fragment.
// A-frag (m16xk8): lane=(mm&7)*4+(kk&3), reg=(mm>>3)+2*(kk>>2)
// B-frag pair (n16xk8): lane=(nn&7)*4+(kk&3), reg=2*((nn>>3)&1)+((kk>>2)&1)
__device__ __forceinline__ void storeA_sw(uint32_t (*A)[2][32][4], int row, int kq,
                                          float4 v, float scale) {
    const int mt  = row >> 4, mm = row & 15;
    const int kt  = (kq >> 3) & 1;
    const int reg = (mm >> 3) + (((kq >> 2) & 1) << 1);
    uint32_t* dst = &A[mt][kt][(mm & 7) << 2][reg];
    dst[0]  = f2tf(v.x * scale);
    dst[4]  = f2tf(v.y * scale);
    dst[8]  = f2tf(v.z * scale);
    dst[12] = f2tf(v.w * scale);
}

__device__ __forceinline__ void storeBk_sw(uint32_t (*B)[2][32][4], int n, int kq, float4 v) {
    const int ntp = n >> 4;
    const int kt  = (kq >> 3) & 1;
    const int reg = (((n >> 3) & 1) << 1) + ((kq >> 2) & 1);
    uint32_t* dst = &B[ntp][kt][(n & 7) << 2][reg];
    dst[0] = f2tf(v.x); dst[4] = f2tf(v.y); dst[8] = f2tf(v.z); dst[12] = f2tf(v.w);
}

__device__ __forceinline__ void storeBn_sw(uint32_t (*B)[2][32][4], int k, int c4, float4 v) {
    const int kt = (k >> 3) & 1;
    const int k3 = k & 3;
    const int kr = (k >> 2) & 1;
    float f[4] = {v.x, v.y, v.z, v.w};
#pragma unroll
    for (int e = 0; e < 4; e++) {
        const int n = c4 + e;
        B[n >> 4][kt][((n & 7) << 2) + k3][(((n >> 3) & 1) << 1) + kr] = f2tf(f[e]);
    }
}

// ---------------------------------------------------------------------------
// Projection: C[m,n] = A[m,1024] . W[n,1024] + bias[n]. 128x128 tile, BK=16,
// 8 warps (2m x 4n), warp tile 64x32, double-buffered.
// ---------------------------------------------------------------------------
__global__ __launch_bounds__(256) void proj_tf32(
    const float* __restrict__ A, const float* __restrict__ W,
    const float* __restrict__ bias, float* __restrict__ C, int head_layout)
{
    __shared__ __align__(16) uint32_t As[2][8][2][32][4];
    __shared__ __align__(16) uint32_t Bs[2][8][2][32][4];

    const int t    = threadIdx.x;
    const int m0   = blockIdx.y * 128;
    const int n0   = blockIdx.x * 128;
    const int wid  = t >> 5, lane = t & 31;
    const int wm   = (wid >> 2) * 64;
    const int wn   = (wid & 3) * 32;
    const int g    = lane >> 2, tg = lane & 3;
    const int mt0  = wm >> 4, ntp0 = wn >> 4;

    const int f0 = t * 2, f1 = t * 2 + 1;
    const int r0 = f0 >> 2, kq0 = (f0 & 3) * 4;
    const int r1 = f1 >> 2, kq1 = (f1 & 3) * 4;
    const float* Ap0 = A + (size_t)(m0 + r0) * DD + kq0;
    const float* Ap1 = A + (size_t)(m0 + r1) * DD + kq1;
    const float* Wp0 = W + (size_t)(n0 + r0) * DD + kq0;
    const float* Wp1 = W + (size_t)(n0 + r1) * DD + kq1;

    float acc[4][4][4];
#pragma unroll
    for (int i = 0; i < 4; i++)
#pragma unroll
        for (int j = 0; j < 4; j++)
#pragma unroll
            for (int r = 0; r < 4; r++) acc[i][j][r] = 0.f;

    const int NST = DD / 16;  // 64
    float4 pa0 = *(const float4*)Ap0, pa1 = *(const float4*)Ap1;
    float4 pb0 = *(const float4*)Wp0, pb1 = *(const float4*)Wp1;
    storeA_sw(As[0], r0, kq0, pa0, 1.f); storeA_sw(As[0], r1, kq1, pa1, 1.f);
    storeBk_sw(Bs[0], r0, kq0, pb0);     storeBk_sw(Bs[0], r1, kq1, pb1);
    __syncthreads();

    for (int s = 0; s < NST; s++) {
        if (s + 1 < NST) {
            const int off = (s + 1) * 16;
            pa0 = *(const float4*)(Ap0 + off); pa1 = *(const float4*)(Ap1 + off);
            pb0 = *(const float4*)(Wp0 + off); pb1 = *(const float4*)(Wp1 + off);
        }
        const int buf = s & 1;
#pragma unroll
        for (int kt = 0; kt < 2; kt++) {
            uint4 av[4], bv[2];
#pragma unroll
            for (int i = 0; i < 4; i++)
                av[i] = *(const uint4*)&As[buf][mt0 + i][kt][lane][0];
#pragma unroll
            for (int p = 0; p < 2; p++)
                bv[p] = *(const uint4*)&Bs[buf][ntp0 + p][kt][lane][0];
#pragma unroll
            for (int i = 0; i < 4; i++) {
                const uint32_t* a = (const uint32_t*)&av[i];
#pragma unroll
                for (int p = 0; p < 2; p++) {
                    uint32_t b0[2] = {bv[p].x, bv[p].y};
                    uint32_t b1[2] = {bv[p].z, bv[p].w};
                    mma_tf32(acc[i][2 * p + 0], a, b0);
                    mma_tf32(acc[i][2 * p + 1], a, b1);
                }
            }
        }
        if (s + 1 < NST) {
            const int nb = (s + 1) & 1;
            storeA_sw(As[nb], r0, kq0, pa0, 1.f); storeA_sw(As[nb], r1, kq1, pa1, 1.f);
            storeBk_sw(Bs[nb], r0, kq0, pb0);     storeBk_sw(Bs[nb], r1, kq1, pb1);
        }
        __syncthreads();
    }

#pragma unroll
    for (int i = 0; i < 4; i++) {
#pragma unroll
        for (int j = 0; j < 4; j++) {
            const int n = n0 + wn + j * 8 + 2 * tg;
#pragma unroll
            for (int half = 0; half < 2; half++) {
                const int m = m0 + wm + i * 16 + g + half * 8;
                const float v0 = acc[i][j][half * 2 + 0] + bias[n];
                const float v1 = acc[i][j][half * 2 + 1] + bias[n + 1];
                if (head_layout) {
                    const int bb = m / SS, s_ = m % SS;
                    const int h0 = n / DEPTH, d0 = n % DEPTH;
                    const int h1 = (n + 1) / DEPTH, d1 = (n + 1) % DEPTH;
                    C[(((size_t)(bb * HH + h0)) * SS + s_) * DEPTH + d0] = v0;
                    C[(((size_t)(bb * HH + h1)) * SS + s_) * DEPTH + d1] = v1;
                } else {
                    C[(size_t)m * DD + n]     = v0;
                    C[(size_t)m * DD + n + 1] = v1;
                }
            }
        }
    }
}

// ---------------------------------------------------------------------------
// attn[bh,q,k] = (k<=q) ? exp(dot(Q,K)/8) : 0   (unnormalized; exp fused)
// ---------------------------------------------------------------------------
__global__ __launch_bounds__(256) void attn_logits_exp(
    const float* __restrict__ Qh, const float* __restrict__ Kh,
    float* __restrict__ attn)
{
    const int bh = blockIdx.z;
    const int tq = blockIdx.y;
    const int tk = blockIdx.x;
    const int t  = threadIdx.x;

    const size_t abase = ((size_t)bh * SS + (size_t)tq * 128) * SS + (size_t)tk * 128;

    if (tk > tq) {
        float4 z = make_float4(0.f, 0.f, 0.f, 0.f);
        float* base = attn + abase;
        for (int idx = t; idx < 128 * 32; idx += 256) {
            const int row = idx >> 5, c4 = (idx & 31) * 4;
            *(float4*)&base[(size_t)row * SS + c4] = z;
        }
        return;
    }

    __shared__ __align__(16) uint32_t As[2][8][2][32][4];
    __shared__ __align__(16) uint32_t Bs[2][8][2][32][4];

    const float* Qb = Qh + ((size_t)bh * SS + (size_t)tq * 128) * DEPTH;
    const float* Kb = Kh + ((size_t)bh * SS + (size_t)tk * 128) * DEPTH;

    const int wid = t >> 5, lane = t & 31;
    const int wm  = (wid >> 2) * 64;
    const int wn  = (wid & 3) * 32;
    const int g   = lane >> 2, tg = lane & 3;
    const int mt0 = wm >> 4, ntp0 = wn >> 4;

    const int f0 = t * 2, f1 = t * 2 + 1;
    const int r0 = f0 >> 2, kq0 = (f0 & 3) * 4;
    const int r1 = f1 >> 2, kq1 = (f1 & 3) * 4;
    const float* Qp0 = Qb + (size_t)r0 * DEPTH + kq0;
    const float* Qp1 = Qb + (size_t)r1 * DEPTH + kq1;
    const float* Kp0 = Kb + (size_t)r0 * DEPTH + kq0;
    const float* Kp1 = Kb + (size_t)r1 * DEPTH + kq1;

    float acc[4][4][4];
#pragma unroll
    for (int i = 0; i < 4; i++)
#pragma unroll
        for (int j = 0; j < 4; j++)
#pragma unroll
            for (int r = 0; r < 4; r++) acc[i][j][r] = 0.f;

    const int NST = DEPTH / 16;  // 4
    float4 pa0 = *(const float4*)Qp0, pa1 = *(const float4*)Qp1;
    float4 pb0 = *(const float4*)Kp0, pb1 = *(const float4*)Kp1;
    storeA_sw(As[0], r0, kq0, pa0, 0.125f); storeA_sw(As[0], r1, kq1, pa1, 0.125f);
    storeBk_sw(Bs[0], r0, kq0, pb0);        storeBk_sw(Bs[0], r1, kq1, pb1);
    __syncthreads();

    for (int s = 0; s < NST; s++) {
        if (s + 1 < NST) {
            const int off = (s + 1) * 16;
            pa0 = *(const float4*)(Qp0 + off); pa1 = *(const float4*)(Qp1 + off);
            pb0 = *(const float4*)(Kp0 + off); pb1 = *(const float4*)(Kp1 + off);
        }
        const int buf = s & 1;
#pragma unroll
        for (int kt = 0; kt < 2; kt++) {
            uint4 av[4], bv[2];
#pragma unroll
            for (int i = 0; i < 4; i++)
                av[i] = *(const uint4*)&As[buf][mt0 + i][kt][lane][0];
#pragma unroll
            for (int p = 0; p < 2; p++)
                bv[p] = *(const uint4*)&Bs[buf][ntp0 + p][kt][lane][0];
#pragma unroll
            for (int i = 0; i < 4; i++) {
                const uint32_t* a = (const uint32_t*)&av[i];
#pragma unroll
                for (int p = 0; p < 2; p++) {
                    uint32_t b0[2] = {bv[p].x, bv[p].y};
                    uint32_t b1[2] = {bv[p].z, bv[p].w};
                    mma_tf32(acc[i][2 * p + 0], a, b0);
                    mma_tf32(acc[i][2 * p + 1], a, b1);
                }
            }
        }
        if (s + 1 < NST) {
            const int nb = (s + 1) & 1;
            storeA_sw(As[nb], r0, kq0, pa0, 0.125f); storeA_sw(As[nb], r1, kq1, pa1, 0.125f);
            storeBk_sw(Bs[nb], r0, kq0, pb0);        storeBk_sw(Bs[nb], r1, kq1, pb1);
        }
        __syncthreads();
    }

    const int qg0 = tq * 128, kg0 = tk * 128;
#pragma unroll
    for (int i = 0; i < 4; i++) {
#pragma unroll
        for (int j = 0; j < 4; j++) {
            const int kn = wn + j * 8 + 2 * tg;
#pragma unroll
            for (int half = 0; half < 2; half++) {
                const int qm = wm + i * 16 + g + half * 8;
                const int qg = qg0 + qm;
                const float v0 = (kg0 + kn     <= qg) ? __expf(acc[i][j][half * 2 + 0]) : 0.f;
                const float v1 = (kg0 + kn + 1 <= qg) ? __expf(acc[i][j][half * 2 + 1]) : 0.f;
                attn[abase + (size_t)qm * SS + kn]     = v0;
                attn[abase + (size_t)qm * SS + kn + 1] = v1;
            }
        }
    }
}

// ---------------------------------------------------------------------------
// One pass: sum the causal prefix (rounded up to 4; tail is exact zeros),
// then scale by 1/sum.
// ---------------------------------------------------------------------------
__global__ __launch_bounds__(128) void normalize_rows(float* __restrict__ attn)
{
    const size_t row = blockIdx.x;
    const int q  = (int)(row % SS);
    const int n4 = ((q + 4) & ~3) >> 2;   // float4 count covering q+1
    float4* p = (float4*)(attn + row * SS);
    const int t = threadIdx.x;

    __shared__ float red[4];

    float s = 0.f;
    for (int i = t; i < n4; i += 128) {
        float4 v = p[i];
        s += (v.x + v.y) + (v.z + v.w);
    }
#pragma unroll
    for (int o = 16; o; o >>= 1) s += __shfl_xor_sync(0xffffffffu, s, o);
    if ((t & 31) == 0) red[t >> 5] = s;
    __syncthreads();
    const float inv = 1.0f / (red[0] + red[1] + red[2] + red[3]);

    for (int i = t; i < n4; i += 128) {
        float4 v = p[i];
        v.x *= inv; v.y *= inv; v.z *= inv; v.w *= inv;
        p[i] = v;
    }
}

// ---------------------------------------------------------------------------
// ctx[b,q,h*64+c] = sum_k attn[bh,q,k] * V[bh,k,c].  128x64 tile, BK=16,
// 8 warps (4m x 2n), warp tile 32x32, double-buffered, causal k bound.
// ---------------------------------------------------------------------------
__global__ __launch_bounds__(256) void attn_ctx_tf32(
    const float* __restrict__ attn, const float* __restrict__ Vh,
    float* __restrict__ ctx)
{
    const int tq = blockIdx.x;
    const int bh = blockIdx.y;
    const int bb = bh / HH, h = bh % HH;
    const int t  = threadIdx.x;

    __shared__ __align__(16) uint32_t As[2][8][2][32][4];
    __shared__ __align__(16) uint32_t Bs[2][4][2][32][4];

    const float* arow = attn + ((size_t)bh * SS + (size_t)tq * 128) * SS;
    const float* Vb   = Vh + (size_t)bh * SS * DEPTH;

    const int wid = t >> 5, lane = t & 31;
    const int wm  = (wid >> 1) * 32;
    const int wn  = (wid & 1) * 32;
    const int g   = lane >> 2, tg = lane & 3;
    const int mt0 = wm >> 4, ntp0 = wn >> 4;

    const int f0 = t * 2, f1 = t * 2 + 1;
    const int r0 = f0 >> 2, kq0 = (f0 & 3) * 4;
    const int r1 = f1 >> 2, kq1 = (f1 & 3) * 4;
    const float* Ap0 = arow + (size_t)r0 * SS + kq0;
    const float* Ap1 = arow + (size_t)r1 * SS + kq1;
    const int vk = t >> 4, vc4 = (t & 15) * 4;         // V tile 16x64 loader
    const float* Vp = Vb + (size_t)vk * DEPTH + vc4;

    float acc[2][4][4];
#pragma unroll
    for (int i = 0; i < 2; i++)
#pragma unroll
        for (int j = 0; j < 4; j++)
#pragma unroll
            for (int r = 0; r < 4; r++) acc[i][j][r] = 0.f;

    const int NST = (tq + 1) * 8;
    float4 pa0 = *(const float4*)Ap0, pa1 = *(const float4*)Ap1;
    float4 pv  = *(const float4*)Vp;
    storeA_sw(As[0], r0, kq0, pa0, 1.f); storeA_sw(As[0], r1, kq1, pa1, 1.f);
    storeBn_sw(Bs[0], vk, vc4, pv);
    __syncthreads();

    for (int s = 0; s < NST; s++) {
        if (s + 1 < NST) {
            const int off = (s + 1) * 16;
            pa0 = *(const float4*)(Ap0 + off);
            pa1 = *(const float4*)(Ap1 + off);
            pv  = *(const float4*)(Vp + (size_t)off * DEPTH);
        }
        const int buf = s & 1;
#pragma unroll
        for (int kt = 0; kt < 2; kt++) {
            uint4 av[2], bv[2];
#pragma unroll
            for (int i = 0; i < 2; i++)
                av[i] = *(const uint4*)&As[buf][mt0 + i][kt][lane][0];
#pragma unroll
            for (int p = 0; p < 2; p++)
                bv[p] = *(const uint4*)&Bs[buf][ntp0 + p][kt][lane][0];
#pragma unroll
            for (int i = 0; i < 2; i++) {
                const uint32_t* a = (const uint32_t*)&av[i];
#pragma unroll
                for (int p = 0; p < 2; p++) {
                    uint32_t b0[2] = {bv[p].x, bv[p].y};
                    uint32_t b1[2] = {bv[p].z, bv[p].w};
                    mma_tf32(acc[i][2 * p + 0], a, b0);
                    mma_tf32(acc[i][2 * p + 1], a, b1);
                }
            }
        }
        if (s + 1 < NST) {
            const int nb = (s + 1) & 1;
            storeA_sw(As[nb], r0, kq0, pa0, 1.f); storeA_sw(As[nb], r1, kq1, pa1, 1.f);
            storeBn_sw(Bs[nb], vk, vc4, pv);
        }
        __syncthreads();
    }

#pragma unroll
    for (int i = 0; i < 2; i++) {
#pragma unroll
        for (int j = 0; j < 4; j++) {
            const int c = wn + j * 8 + 2 * tg;
#pragma unroll
            for (int half = 0; half < 2; half++) {
                const int q = tq * 128 + wm + i * 16 + g + half * 8;
                float* dst = &ctx[((size_t)bb * SS + q) * DD + h * DEPTH + c];
                dst[0] = acc[i][j][half * 2 + 0];
                dst[1] = acc[i][j][half * 2 + 1];
            }
        }
    }
}

// ---------------------------------------------------------------------------
extern "C" void kernel_launch(void* const* d_in, const int* in_sizes, int n_in,
                              void* d_out, int out_size)
{
    const float* q    = (const float*)d_in[0];
    const float* k    = (const float*)d_in[1];
    const float* v    = (const float*)d_in[2];
    // d_in[3] = mask (causal; applied analytically)
    const float* wq   = (const float*)d_in[4];
    const float* bq   = (const float*)d_in[5];
    const float* wk   = (const float*)d_in[6];
    const float* bk   = (const float*)d_in[7];
    const float* wv   = (const float*)d_in[8];
    const float* bv   = (const float*)d_in[9];
    const float* wo   = (const float*)d_in[10];
    const float* bo   = (const float*)d_in[11];
    float* out = (float*)d_out;

    float *gq, *gk, *gv, *gctx, *gattn;
    cudaGetSymbolAddress((void**)&gq,   g_q);
    cudaGetSymbolAddress((void**)&gk,   g_k);
    cudaGetSymbolAddress((void**)&gv,   g_v);
    cudaGetSymbolAddress((void**)&gctx, g_ctx);
    cudaGetSymbolAddress((void**)&gattn, g_attn_fb);

    const long long OUT_E = (long long)BB * SS * DD;
    const long long ATT_E = (long long)BB * HH * SS * SS;
    float* attn = ((long long)out_size >= OUT_E + ATT_E) ? (out + OUT_E) : gattn;

    const dim3 gproj(DD / 128, MTOT / 128);

    proj_tf32<<<gproj, 256>>>(q, wq, bq, gq, 1);
    proj_tf32<<<gproj, 256>>>(k, wk, bk, gk, 1);
    proj_tf32<<<gproj, 256>>>(v, wv, bv, gv, 1);

    attn_logits_exp<<<dim3(SS / 128, SS / 128, BB * HH), 256>>>(gq, gk, attn);
    normalize_rows<<<BB * HH * SS, 128>>>(attn);
    attn_ctx_tf32<<<dim3(SS / 128, BB * HH), 256>>>(attn, gv, gctx);

    proj_tf32<<<gproj, 256>>>(gctx, wo, bo, out, 0);
}

// round 5
// speedup vs baseline: 1.2679x; 1.2679x over previous
#include <cuda_runtime.h>
#include <cstdint>

#define BB    4
#define SS    2048
#define DD    1024
#define HH    16
#define DEPTH 64
#define MTOT  (BB * SS)

__device__ float g_q  [(size_t)BB * HH * SS * DEPTH];
__device__ float g_k  [(size_t)BB * HH * SS * DEPTH];
__device__ float g_v  [(size_t)BB * HH * SS * DEPTH];
__device__ float g_ctx[(size_t)BB * SS * DD];
__device__ float g_attn_fb[(size_t)BB * HH * SS * SS];

// ---------------------------------------------------------------------------
__device__ __forceinline__ uint32_t f2tf(float x) {
    uint32_t r;
    asm("cvt.rna.tf32.f32 %0, %1;" : "=r"(r) : "f"(x));
    return r;
}

__device__ __forceinline__ void mma_tf32(float* c, const uint32_t* a, const uint32_t* b) {
    asm volatile(
        "mma.sync.aligned.m16n8k8.row.col.f32.tf32.tf32.f32 "
        "{%0,%1,%2,%3}, {%4,%5,%6,%7}, {%8,%9}, {%0,%1,%2,%3};"
        : "+f"(c[0]), "+f"(c[1]), "+f"(c[2]), "+f"(c[3])
        : "r"(a[0]), "r"(a[1]), "r"(a[2]), "r"(a[3]), "r"(b[0]), "r"(b[1]));
}

__device__ __forceinline__ uint4 tf4(float4 v, float s) {
    return make_uint4(f2tf(v.x * s), f2tf(v.y * s), f2tf(v.z * s), f2tf(v.w * s));
}

// ---------------------------------------------------------------------------
// Projection: C[m,n] = A[m,1024].W[n,1024] + bias[n].
// 128 threads (4 warps, 2x2), block 128x128, warp tile 64x64, BK=16,
// 2-buffer smem + register prefetch. Layout As[m][k] pad-20 (conflict-free).
// ---------------------------------------------------------------------------
__global__ __launch_bounds__(128, 2) void proj_tf32(
    const float* __restrict__ A, const float* __restrict__ W,
    const float* __restrict__ bias, float* __restrict__ C, int head_layout)
{
    __shared__ uint32_t As[2][128][20];
    __shared__ uint32_t Bs[2][128][20];

    const int t   = threadIdx.x;
    const int m0  = blockIdx.y * 128;
    const int n0  = blockIdx.x * 128;
    const int wid = t >> 5, lane = t & 31;
    const int wm  = (wid >> 1) * 64;
    const int wn  = (wid & 1) * 64;
    const int g   = lane >> 2, tg = lane & 3;

    const float* Arow = A + (size_t)(m0 + t) * DD;
    const float* Wrow = W + (size_t)(n0 + t) * DD;

    float acc[4][8][4];
#pragma unroll
    for (int i = 0; i < 4; i++)
#pragma unroll
        for (int j = 0; j < 8; j++)
#pragma unroll
            for (int r = 0; r < 4; r++) acc[i][j][r] = 0.f;

    const int NST = DD / 16;  // 64
    float4 pa[4], pb[4];
#pragma unroll
    for (int u = 0; u < 4; u++) {
        pa[u] = *(const float4*)(Arow + u * 4);
        pb[u] = *(const float4*)(Wrow + u * 4);
    }
#pragma unroll
    for (int u = 0; u < 4; u++) {
        *(uint4*)&As[0][t][u * 4] = tf4(pa[u], 1.f);
        *(uint4*)&Bs[0][t][u * 4] = tf4(pb[u], 1.f);
    }
    __syncthreads();

    for (int s = 0; s < NST; s++) {
        if (s + 1 < NST) {
            const int off = (s + 1) * 16;
#pragma unroll
            for (int u = 0; u < 4; u++) {
                pa[u] = *(const float4*)(Arow + off + u * 4);
                pb[u] = *(const float4*)(Wrow + off + u * 4);
            }
        }
        const int buf = s & 1;
#pragma unroll
        for (int ks = 0; ks < 16; ks += 8) {
            uint32_t a[4][4], b[8][2];
#pragma unroll
            for (int i = 0; i < 4; i++) {
                const int r = wm + i * 16;
                a[i][0] = As[buf][r + g][ks + tg];
                a[i][1] = As[buf][r + g + 8][ks + tg];
                a[i][2] = As[buf][r + g][ks + tg + 4];
                a[i][3] = As[buf][r + g + 8][ks + tg + 4];
            }
#pragma unroll
            for (int j = 0; j < 8; j++) {
                const int n = wn + j * 8;
                b[j][0] = Bs[buf][n + g][ks + tg];
                b[j][1] = Bs[buf][n + g][ks + tg + 4];
            }
#pragma unroll
            for (int i = 0; i < 4; i++)
#pragma unroll
                for (int j = 0; j < 8; j++)
                    mma_tf32(acc[i][j], a[i], b[j]);
        }
        if (s + 1 < NST) {
            const int nb = (s + 1) & 1;
#pragma unroll
            for (int u = 0; u < 4; u++) {
                *(uint4*)&As[nb][t][u * 4] = tf4(pa[u], 1.f);
                *(uint4*)&Bs[nb][t][u * 4] = tf4(pb[u], 1.f);
            }
        }
        __syncthreads();
    }

#pragma unroll
    for (int i = 0; i < 4; i++) {
#pragma unroll
        for (int j = 0; j < 8; j++) {
            const int n = n0 + wn + j * 8 + 2 * tg;
#pragma unroll
            for (int half = 0; half < 2; half++) {
                const int m = m0 + wm + i * 16 + g + half * 8;
                const float v0 = acc[i][j][half * 2 + 0] + bias[n];
                const float v1 = acc[i][j][half * 2 + 1] + bias[n + 1];
                if (head_layout) {
                    const int bb = m / SS, s_ = m % SS;
                    const int h0 = n / DEPTH, d0 = n % DEPTH;
                    const int h1 = (n + 1) / DEPTH, d1 = (n + 1) % DEPTH;
                    C[(((size_t)(bb * HH + h0)) * SS + s_) * DEPTH + d0] = v0;
                    C[(((size_t)(bb * HH + h1)) * SS + s_) * DEPTH + d1] = v1;
                } else {
                    C[(size_t)m * DD + n]     = v0;
                    C[(size_t)m * DD + n + 1] = v1;
                }
            }
        }
    }
}

// ---------------------------------------------------------------------------
// attn[bh,q,k] = (k<=q) ? exp(dot(Q,K)/8) : 0   (unnormalized; exp fused)
// 128 threads, block 128x128, warp tile 64x64, BK=16 over DEPTH=64.
// ---------------------------------------------------------------------------
__global__ __launch_bounds__(128, 2) void attn_logits_exp(
    const float* __restrict__ Qh, const float* __restrict__ Kh,
    float* __restrict__ attn)
{
    const int bh = blockIdx.z;
    const int tq = blockIdx.y;
    const int tk = blockIdx.x;
    const int t  = threadIdx.x;

    const size_t abase = ((size_t)bh * SS + (size_t)tq * 128) * SS + (size_t)tk * 128;

    if (tk > tq) {
        float4 z = make_float4(0.f, 0.f, 0.f, 0.f);
        float* base = attn + abase;
        for (int idx = t; idx < 128 * 32; idx += 128) {
            const int row = idx >> 5, c4 = (idx & 31) * 4;
            *(float4*)&base[(size_t)row * SS + c4] = z;
        }
        return;
    }

    __shared__ uint32_t As[2][128][20];
    __shared__ uint32_t Bs[2][128][20];

    const float* Qrow = Qh + ((size_t)bh * SS + (size_t)tq * 128 + t) * DEPTH;
    const float* Krow = Kh + ((size_t)bh * SS + (size_t)tk * 128 + t) * DEPTH;

    const int wid = t >> 5, lane = t & 31;
    const int wm  = (wid >> 1) * 64;
    const int wn  = (wid & 1) * 64;
    const int g   = lane >> 2, tg = lane & 3;

    float acc[4][8][4];
#pragma unroll
    for (int i = 0; i < 4; i++)
#pragma unroll
        for (int j = 0; j < 8; j++)
#pragma unroll
            for (int r = 0; r < 4; r++) acc[i][j][r] = 0.f;

    const int NST = DEPTH / 16;  // 4
    float4 pa[4], pb[4];
#pragma unroll
    for (int u = 0; u < 4; u++) {
        pa[u] = *(const float4*)(Qrow + u * 4);
        pb[u] = *(const float4*)(Krow + u * 4);
    }
#pragma unroll
    for (int u = 0; u < 4; u++) {
        *(uint4*)&As[0][t][u * 4] = tf4(pa[u], 0.125f);   // fold 1/8 into Q
        *(uint4*)&Bs[0][t][u * 4] = tf4(pb[u], 1.f);
    }
    __syncthreads();

    for (int s = 0; s < NST; s++) {
        if (s + 1 < NST) {
            const int off = (s + 1) * 16;
#pragma unroll
            for (int u = 0; u < 4; u++) {
                pa[u] = *(const float4*)(Qrow + off + u * 4);
                pb[u] = *(const float4*)(Krow + off + u * 4);
            }
        }
        const int buf = s & 1;
#pragma unroll
        for (int ks = 0; ks < 16; ks += 8) {
            uint32_t a[4][4], b[8][2];
#pragma unroll
            for (int i = 0; i < 4; i++) {
                const int r = wm + i * 16;
                a[i][0] = As[buf][r + g][ks + tg];
                a[i][1] = As[buf][r + g + 8][ks + tg];
                a[i][2] = As[buf][r + g][ks + tg + 4];
                a[i][3] = As[buf][r + g + 8][ks + tg + 4];
            }
#pragma unroll
            for (int j = 0; j < 8; j++) {
                const int n = wn + j * 8;
                b[j][0] = Bs[buf][n + g][ks + tg];
                b[j][1] = Bs[buf][n + g][ks + tg + 4];
            }
#pragma unroll
            for (int i = 0; i < 4; i++)
#pragma unroll
                for (int j = 0; j < 8; j++)
                    mma_tf32(acc[i][j], a[i], b[j]);
        }
        if (s + 1 < NST) {
            const int nb = (s + 1) & 1;
#pragma unroll
            for (int u = 0; u < 4; u++) {
                *(uint4*)&As[nb][t][u * 4] = tf4(pa[u], 0.125f);
                *(uint4*)&Bs[nb][t][u * 4] = tf4(pb[u], 1.f);
            }
        }
        __syncthreads();
    }

    const int qg0 = tq * 128, kg0 = tk * 128;
#pragma unroll
    for (int i = 0; i < 4; i++) {
#pragma unroll
        for (int j = 0; j < 8; j++) {
            const int kn = wn + j * 8 + 2 * tg;
#pragma unroll
            for (int half = 0; half < 2; half++) {
                const int qm = wm + i * 16 + g + half * 8;
                const int qg = qg0 + qm;
                const float v0 = (kg0 + kn     <= qg) ? __expf(acc[i][j][half * 2 + 0]) : 0.f;
                const float v1 = (kg0 + kn + 1 <= qg) ? __expf(acc[i][j][half * 2 + 1]) : 0.f;
                attn[abase + (size_t)qm * SS + kn]     = v0;
                attn[abase + (size_t)qm * SS + kn + 1] = v1;
            }
        }
    }
}

// ---------------------------------------------------------------------------
// One pass: sum causal prefix, scale by 1/sum (tail is exact zeros).
// ---------------------------------------------------------------------------
__global__ __launch_bounds__(128) void normalize_rows(float* __restrict__ attn)
{
    const size_t row = blockIdx.x;
    const int q  = (int)(row % SS);
    const int n4 = ((q + 4) & ~3) >> 2;
    float4* p = (float4*)(attn + row * SS);
    const int t = threadIdx.x;

    __shared__ float red[4];

    float s = 0.f;
    for (int i = t; i < n4; i += 128) {
        float4 v = p[i];
        s += (v.x + v.y) + (v.z + v.w);
    }
#pragma unroll
    for (int o = 16; o; o >>= 1) s += __shfl_xor_sync(0xffffffffu, s, o);
    if ((t & 31) == 0) red[t >> 5] = s;
    __syncthreads();
    const float inv = 1.0f / (red[0] + red[1] + red[2] + red[3]);

    for (int i = t; i < n4; i += 128) {
        float4 v = p[i];
        v.x *= inv; v.y *= inv; v.z *= inv; v.w *= inv;
        p[i] = v;
    }
}

// ---------------------------------------------------------------------------
// ctx[b,q,h*64+c] = sum_k attn[bh,q,k] * V[bh,k,c].
// 128 threads (4 warps, 2x2), block 128x64, warp tile 64x32, BK=16,
// causal k bound, 2-buffer + register prefetch.
// ---------------------------------------------------------------------------
__global__ __launch_bounds__(128, 2) void attn_ctx_tf32(
    const float* __restrict__ attn, const float* __restrict__ Vh,
    float* __restrict__ ctx)
{
    const int tq = blockIdx.x;
    const int bh = blockIdx.y;
    const int bb = bh / HH, h = bh % HH;
    const int t  = threadIdx.x;

    __shared__ uint32_t As[2][128][20];
    __shared__ uint32_t Vs[2][16][68];

    const float* arow = attn + ((size_t)bh * SS + (size_t)tq * 128 + t) * SS;
    const float* Vb   = Vh + (size_t)bh * SS * DEPTH;

    const int wid = t >> 5, lane = t & 31;
    const int wm  = (wid >> 1) * 64;
    const int wn  = (wid & 1) * 32;
    const int g   = lane >> 2, tg = lane & 3;

    // V loader: 16x64 per stage, 2 float4 per thread
    const int vr0 = (t * 2)     >> 4, vc0 = ((t * 2)     & 15) * 4;
    const int vr1 = (t * 2 + 1) >> 4, vc1 = ((t * 2 + 1) & 15) * 4;

    float acc[4][4][4];
#pragma unroll
    for (int i = 0; i < 4; i++)
#pragma unroll
        for (int j = 0; j < 4; j++)
#pragma unroll
            for (int r = 0; r < 4; r++) acc[i][j][r] = 0.f;

    const int NST = (tq + 1) * 8;
    float4 pa[4], pv0, pv1;
#pragma unroll
    for (int u = 0; u < 4; u++) pa[u] = *(const float4*)(arow + u * 4);
    pv0 = *(const float4*)(Vb + (size_t)vr0 * DEPTH + vc0);
    pv1 = *(const float4*)(Vb + (size_t)vr1 * DEPTH + vc1);
#pragma unroll
    for (int u = 0; u < 4; u++) *(uint4*)&As[0][t][u * 4] = tf4(pa[u], 1.f);
    *(uint4*)&Vs[0][vr0][vc0] = tf4(pv0, 1.f);
    *(uint4*)&Vs[0][vr1][vc1] = tf4(pv1, 1.f);
    __syncthreads();

    for (int s = 0; s < NST; s++) {
        if (s + 1 < NST) {
            const int off = (s + 1) * 16;
#pragma unroll
            for (int u = 0; u < 4; u++)
                pa[u] = *(const float4*)(arow + off + u * 4);
            pv0 = *(const float4*)(Vb + (size_t)(off + vr0) * DEPTH + vc0);
            pv1 = *(const float4*)(Vb + (size_t)(off + vr1) * DEPTH + vc1);
        }
        const int buf = s & 1;
#pragma unroll
        for (int ks = 0; ks < 16; ks += 8) {
            uint32_t a[4][4], b[4][2];
#pragma unroll
            for (int i = 0; i < 4; i++) {
                const int r = wm + i * 16;
                a[i][0] = As[buf][r + g][ks + tg];
                a[i][1] = As[buf][r + g + 8][ks + tg];
                a[i][2] = As[buf][r + g][ks + tg + 4];
                a[i][3] = As[buf][r + g + 8][ks + tg + 4];
            }
#pragma unroll
            for (int j = 0; j < 4; j++) {
                const int n = wn + j * 8;
                b[j][0] = Vs[buf][ks + tg][n + g];
                b[j][1] = Vs[buf][ks + tg + 4][n + g];
            }
#pragma unroll
            for (int i = 0; i < 4; i++)
#pragma unroll
                for (int j = 0; j < 4; j++)
                    mma_tf32(acc[i][j], a[i], b[j]);
        }
        if (s + 1 < NST) {
            const int nb = (s + 1) & 1;
#pragma unroll
            for (int u = 0; u < 4; u++) *(uint4*)&As[nb][t][u * 4] = tf4(pa[u], 1.f);
            *(uint4*)&Vs[nb][vr0][vc0] = tf4(pv0, 1.f);
            *(uint4*)&Vs[nb][vr1][vc1] = tf4(pv1, 1.f);
        }
        __syncthreads();
    }

#pragma unroll
    for (int i = 0; i < 4; i++) {
#pragma unroll
        for (int j = 0; j < 4; j++) {
            const int c = wn + j * 8 + 2 * tg;
#pragma unroll
            for (int half = 0; half < 2; half++) {
                const int q = tq * 128 + wm + i * 16 + g + half * 8;
                float* dst = &ctx[((size_t)bb * SS + q) * DD + h * DEPTH + c];
                dst[0] = acc[i][j][half * 2 + 0];
                dst[1] = acc[i][j][half * 2 + 1];
            }
        }
    }
}

// ---------------------------------------------------------------------------
extern "C" void kernel_launch(void* const* d_in, const int* in_sizes, int n_in,
                              void* d_out, int out_size)
{
    const float* q    = (const float*)d_in[0];
    const float* k    = (const float*)d_in[1];
    const float* v    = (const float*)d_in[2];
    // d_in[3] = mask (causal; applied analytically)
    const float* wq   = (const float*)d_in[4];
    const float* bq   = (const float*)d_in[5];
    const float* wk   = (const float*)d_in[6];
    const float* bk   = (const float*)d_in[7];
    const float* wv   = (const float*)d_in[8];
    const float* bv   = (const float*)d_in[9];
    const float* wo   = (const float*)d_in[10];
    const float* bo   = (const float*)d_in[11];
    float* out = (float*)d_out;

    float *gq, *gk, *gv, *gctx, *gattn;
    cudaGetSymbolAddress((void**)&gq,   g_q);
    cudaGetSymbolAddress((void**)&gk,   g_k);
    cudaGetSymbolAddress((void**)&gv,   g_v);
    cudaGetSymbolAddress((void**)&gctx, g_ctx);
    cudaGetSymbolAddress((void**)&gattn, g_attn_fb);

    const long long OUT_E = (long long)BB * SS * DD;
    const long long ATT_E = (long long)BB * HH * SS * SS;
    float* attn = ((long long)out_size >= OUT_E + ATT_E) ? (out + OUT_E) : gattn;

    const dim3 gproj(DD / 128, MTOT / 128);

    proj_tf32<<<gproj, 128>>>(q, wq, bq, gq, 1);
    proj_tf32<<<gproj, 128>>>(k, wk, bk, gk, 1);
    proj_tf32<<<gproj, 128>>>(v, wv, bv, gv, 1);

    attn_logits_exp<<<dim3(SS / 128, SS / 128, BB * HH), 128>>>(gq, gk, attn);
    normalize_rows<<<BB * HH * SS, 128>>>(attn);
    attn_ctx_tf32<<<dim3(SS / 128, BB * HH), 128>>>(attn, gv, gctx);

    proj_tf32<<<gproj, 128>>>(gctx, wo, bo, out, 0);
}

// round 6
// speedup vs baseline: 1.3745x; 1.0841x over previous
#include <cuda_runtime.h>
#include <cstdint>

#define BB    4
#define SS    2048
#define DD    1024
#define HH    16
#define DEPTH 64
#define MTOT  (BB * SS)
#define NTK   (SS / 128)   // 16 k-tiles per row

__device__ float g_q  [(size_t)BB * HH * SS * DEPTH];
__device__ float g_k  [(size_t)BB * HH * SS * DEPTH];
__device__ float g_v  [(size_t)BB * HH * SS * DEPTH];
__device__ float g_ctx[(size_t)BB * SS * DD];
__device__ float g_attn_fb[(size_t)BB * HH * SS * SS];
__device__ float g_psum[(size_t)BB * HH * SS * NTK];   // per-row, per-k-tile partial sums

// ---------------------------------------------------------------------------
__device__ __forceinline__ uint32_t f2tf(float x) {
    uint32_t r;
    asm("cvt.rna.tf32.f32 %0, %1;" : "=r"(r) : "f"(x));
    return r;
}

__device__ __forceinline__ void mma_tf32(float* c, const uint32_t* a, const uint32_t* b) {
    asm volatile(
        "mma.sync.aligned.m16n8k8.row.col.f32.tf32.tf32.f32 "
        "{%0,%1,%2,%3}, {%4,%5,%6,%7}, {%8,%9}, {%0,%1,%2,%3};"
        : "+f"(c[0]), "+f"(c[1]), "+f"(c[2]), "+f"(c[3])
        : "r"(a[0]), "r"(a[1]), "r"(a[2]), "r"(a[3]), "r"(b[0]), "r"(b[1]));
}

__device__ __forceinline__ uint4 tf4(float4 v, float s) {
    return make_uint4(f2tf(v.x * s), f2tf(v.y * s), f2tf(v.z * s), f2tf(v.w * s));
}

// ---------------------------------------------------------------------------
// Projection: C[m,n] = A[m,1024].W[n,1024] + bias[n].  (R5 config, unchanged)
// 128 threads (4 warps, 2x2), block 128x128, warp tile 64x64, BK=16.
// ---------------------------------------------------------------------------
__global__ __launch_bounds__(128, 2) void proj_tf32(
    const float* __restrict__ A, const float* __restrict__ W,
    const float* __restrict__ bias, float* __restrict__ C, int head_layout)
{
    __shared__ uint32_t As[2][128][20];
    __shared__ uint32_t Bs[2][128][20];

    const int t   = threadIdx.x;
    const int m0  = blockIdx.y * 128;
    const int n0  = blockIdx.x * 128;
    const int wid = t >> 5, lane = t & 31;
    const int wm  = (wid >> 1) * 64;
    const int wn  = (wid & 1) * 64;
    const int g   = lane >> 2, tg = lane & 3;

    const float* Arow = A + (size_t)(m0 + t) * DD;
    const float* Wrow = W + (size_t)(n0 + t) * DD;

    float acc[4][8][4];
#pragma unroll
    for (int i = 0; i < 4; i++)
#pragma unroll
        for (int j = 0; j < 8; j++)
#pragma unroll
            for (int r = 0; r < 4; r++) acc[i][j][r] = 0.f;

    const int NST = DD / 16;
    float4 pa[4], pb[4];
#pragma unroll
    for (int u = 0; u < 4; u++) {
        pa[u] = *(const float4*)(Arow + u * 4);
        pb[u] = *(const float4*)(Wrow + u * 4);
    }
#pragma unroll
    for (int u = 0; u < 4; u++) {
        *(uint4*)&As[0][t][u * 4] = tf4(pa[u], 1.f);
        *(uint4*)&Bs[0][t][u * 4] = tf4(pb[u], 1.f);
    }
    __syncthreads();

    for (int s = 0; s < NST; s++) {
        if (s + 1 < NST) {
            const int off = (s + 1) * 16;
#pragma unroll
            for (int u = 0; u < 4; u++) {
                pa[u] = *(const float4*)(Arow + off + u * 4);
                pb[u] = *(const float4*)(Wrow + off + u * 4);
            }
        }
        const int buf = s & 1;
#pragma unroll
        for (int ks = 0; ks < 16; ks += 8) {
            uint32_t a[4][4], b[8][2];
#pragma unroll
            for (int i = 0; i < 4; i++) {
                const int r = wm + i * 16;
                a[i][0] = As[buf][r + g][ks + tg];
                a[i][1] = As[buf][r + g + 8][ks + tg];
                a[i][2] = As[buf][r + g][ks + tg + 4];
                a[i][3] = As[buf][r + g + 8][ks + tg + 4];
            }
#pragma unroll
            for (int j = 0; j < 8; j++) {
                const int n = wn + j * 8;
                b[j][0] = Bs[buf][n + g][ks + tg];
                b[j][1] = Bs[buf][n + g][ks + tg + 4];
            }
#pragma unroll
            for (int i = 0; i < 4; i++)
#pragma unroll
                for (int j = 0; j < 8; j++)
                    mma_tf32(acc[i][j], a[i], b[j]);
        }
        if (s + 1 < NST) {
            const int nb = (s + 1) & 1;
#pragma unroll
            for (int u = 0; u < 4; u++) {
                *(uint4*)&As[nb][t][u * 4] = tf4(pa[u], 1.f);
                *(uint4*)&Bs[nb][t][u * 4] = tf4(pb[u], 1.f);
            }
        }
        __syncthreads();
    }

#pragma unroll
    for (int i = 0; i < 4; i++) {
#pragma unroll
        for (int j = 0; j < 8; j++) {
            const int n = n0 + wn + j * 8 + 2 * tg;
#pragma unroll
            for (int half = 0; half < 2; half++) {
                const int m = m0 + wm + i * 16 + g + half * 8;
                const float v0 = acc[i][j][half * 2 + 0] + bias[n];
                const float v1 = acc[i][j][half * 2 + 1] + bias[n + 1];
                if (head_layout) {
                    const int bb = m / SS, s_ = m % SS;
                    const int h0 = n / DEPTH, d0 = n % DEPTH;
                    const int h1 = (n + 1) / DEPTH, d1 = (n + 1) % DEPTH;
                    C[(((size_t)(bb * HH + h0)) * SS + s_) * DEPTH + d0] = v0;
                    C[(((size_t)(bb * HH + h1)) * SS + s_) * DEPTH + d1] = v1;
                } else {
                    C[(size_t)m * DD + n]     = v0;
                    C[(size_t)m * DD + n + 1] = v1;
                }
            }
        }
    }
}

// ---------------------------------------------------------------------------
// attn[bh,q,k] = (k<=q) ? exp(dot(Q,K)/8) : 0   + per-tile row sums to g_psum.
// 256 threads, 8 warps (2m x 4n), warp tile 64x32, BK=16 over DEPTH=64.
// ---------------------------------------------------------------------------
__global__ __launch_bounds__(256) void attn_logits_exp(
    const float* __restrict__ Qh, const float* __restrict__ Kh,
    float* __restrict__ attn, float* __restrict__ psum)
{
    const int bh = blockIdx.z;
    const int tq = blockIdx.y;
    const int tk = blockIdx.x;
    const int t  = threadIdx.x;

    const size_t abase = ((size_t)bh * SS + (size_t)tq * 128) * SS + (size_t)tk * 128;
    float* psrow = psum + ((size_t)bh * SS + (size_t)tq * 128) * NTK + tk;

    if (tk > tq) {
        float4 z = make_float4(0.f, 0.f, 0.f, 0.f);
        float* base = attn + abase;
        for (int idx = t; idx < 128 * 32; idx += 256) {
            const int row = idx >> 5, c4 = (idx & 31) * 4;
            *(float4*)&base[(size_t)row * SS + c4] = z;
        }
        if (t < 128) psrow[(size_t)t * NTK] = 0.f;
        return;
    }

    __shared__ uint32_t Qs[2][128][20];
    __shared__ uint32_t Ks[2][128][20];
    __shared__ float ps_s[128][5];

    const float* Qb = Qh + ((size_t)bh * SS + (size_t)tq * 128) * DEPTH;
    const float* Kb = Kh + ((size_t)bh * SS + (size_t)tk * 128) * DEPTH;

    const int wid = t >> 5, lane = t & 31;
    const int wm  = (wid >> 2) * 64;
    const int wn  = (wid & 3) * 32;
    const int g   = lane >> 2, tg = lane & 3;

    // loader: 2 float4 per thread per stage (512 float4 = 128 rows x 16 cols)
    const int f0 = t * 2, f1 = t * 2 + 1;
    const int r0 = f0 >> 2, kq0 = (f0 & 3) * 4;
    const int r1 = f1 >> 2, kq1 = (f1 & 3) * 4;
    const float* Qp0 = Qb + (size_t)r0 * DEPTH + kq0;
    const float* Qp1 = Qb + (size_t)r1 * DEPTH + kq1;
    const float* Kp0 = Kb + (size_t)r0 * DEPTH + kq0;
    const float* Kp1 = Kb + (size_t)r1 * DEPTH + kq1;

    float acc[4][4][4];
#pragma unroll
    for (int i = 0; i < 4; i++)
#pragma unroll
        for (int j = 0; j < 4; j++)
#pragma unroll
            for (int r = 0; r < 4; r++) acc[i][j][r] = 0.f;

    const int NST = DEPTH / 16;  // 4
    float4 pa0 = *(const float4*)Qp0, pa1 = *(const float4*)Qp1;
    float4 pb0 = *(const float4*)Kp0, pb1 = *(const float4*)Kp1;
    *(uint4*)&Qs[0][r0][kq0] = tf4(pa0, 0.125f);
    *(uint4*)&Qs[0][r1][kq1] = tf4(pa1, 0.125f);
    *(uint4*)&Ks[0][r0][kq0] = tf4(pb0, 1.f);
    *(uint4*)&Ks[0][r1][kq1] = tf4(pb1, 1.f);
    __syncthreads();

    for (int s = 0; s < NST; s++) {
        if (s + 1 < NST) {
            const int off = (s + 1) * 16;
            pa0 = *(const float4*)(Qp0 + off); pa1 = *(const float4*)(Qp1 + off);
            pb0 = *(const float4*)(Kp0 + off); pb1 = *(const float4*)(Kp1 + off);
        }
        const int buf = s & 1;
#pragma unroll
        for (int ks = 0; ks < 16; ks += 8) {
            uint32_t a[4][4], b[4][2];
#pragma unroll
            for (int i = 0; i < 4; i++) {
                const int r = wm + i * 16;
                a[i][0] = Qs[buf][r + g][ks + tg];
                a[i][1] = Qs[buf][r + g + 8][ks + tg];
                a[i][2] = Qs[buf][r + g][ks + tg + 4];
                a[i][3] = Qs[buf][r + g + 8][ks + tg + 4];
            }
#pragma unroll
            for (int j = 0; j < 4; j++) {
                const int n = wn + j * 8;
                b[j][0] = Ks[buf][n + g][ks + tg];
                b[j][1] = Ks[buf][n + g][ks + tg + 4];
            }
#pragma unroll
            for (int i = 0; i < 4; i++)
#pragma unroll
                for (int j = 0; j < 4; j++)
                    mma_tf32(acc[i][j], a[i], b[j]);
        }
        if (s + 1 < NST) {
            const int nb = (s + 1) & 1;
            *(uint4*)&Qs[nb][r0][kq0] = tf4(pa0, 0.125f);
            *(uint4*)&Qs[nb][r1][kq1] = tf4(pa1, 0.125f);
            *(uint4*)&Ks[nb][r0][kq0] = tf4(pb0, 1.f);
            *(uint4*)&Ks[nb][r1][kq1] = tf4(pb1, 1.f);
        }
        __syncthreads();
    }

    // Epilogue: mask + exp, store, accumulate per-row partial sums.
    const int qg0 = tq * 128, kg0 = tk * 128;
    float rowacc[4][2];
#pragma unroll
    for (int i = 0; i < 4; i++) { rowacc[i][0] = 0.f; rowacc[i][1] = 0.f; }

#pragma unroll
    for (int i = 0; i < 4; i++) {
#pragma unroll
        for (int j = 0; j < 4; j++) {
            const int kn = wn + j * 8 + 2 * tg;
#pragma unroll
            for (int half = 0; half < 2; half++) {
                const int qm = wm + i * 16 + g + half * 8;
                const int qg = qg0 + qm;
                const float v0 = (kg0 + kn     <= qg) ? __expf(acc[i][j][half * 2 + 0]) : 0.f;
                const float v1 = (kg0 + kn + 1 <= qg) ? __expf(acc[i][j][half * 2 + 1]) : 0.f;
                attn[abase + (size_t)qm * SS + kn]     = v0;
                attn[abase + (size_t)qm * SS + kn + 1] = v1;
                rowacc[i][half] += v0 + v1;
            }
        }
    }
    // reduce over tg (lanes within quad share a row)
#pragma unroll
    for (int i = 0; i < 4; i++)
#pragma unroll
        for (int half = 0; half < 2; half++) {
            float v = rowacc[i][half];
            v += __shfl_xor_sync(0xffffffffu, v, 1);
            v += __shfl_xor_sync(0xffffffffu, v, 2);
            if (tg == 0) ps_s[wm + i * 16 + g + half * 8][wid & 3] = v;
        }
    __syncthreads();
    if (t < 128) {
        const float s4 = (ps_s[t][0] + ps_s[t][1]) + (ps_s[t][2] + ps_s[t][3]);
        psrow[(size_t)t * NTK] = s4;
    }
}

// ---------------------------------------------------------------------------
// ctx[b,q,h*64+c] = sum_k (attn[bh,q,k]/rowsum) * V[bh,k,c]
// AND writes back normalized attn (attn /= rowsum), eliminating normalize pass.
// 128 threads (4 warps, 2x2), block 128x64, warp tile 64x32, BK=16, causal.
// ---------------------------------------------------------------------------
__global__ __launch_bounds__(128, 2) void attn_ctx_tf32(
    float* __restrict__ attn, const float* __restrict__ Vh,
    const float* __restrict__ psum, float* __restrict__ ctx)
{
    const int tq = blockIdx.x;
    const int bh = blockIdx.y;
    const int bb = bh / HH, h = bh % HH;
    const int t  = threadIdx.x;

    __shared__ uint32_t As[2][128][20];
    __shared__ uint32_t Vs[2][16][68];

    const size_t qrow0 = (size_t)bh * SS + (size_t)tq * 128;
    const float* Vb = Vh + (size_t)bh * SS * DEPTH;

    const int wid = t >> 5, lane = t & 31;
    const int wm  = (wid >> 1) * 64;
    const int wn  = (wid & 1) * 32;
    const int g   = lane >> 2, tg = lane & 3;

    // A loader: thread handles rows rA=(t>>1) and rA+64, cols (t&1)*8 .. +8
    const int rA  = t >> 1;
    const int cA  = (t & 1) * 8;
    float* Aw0 = attn + (qrow0 + rA) * SS + cA;
    float* Aw1 = attn + (qrow0 + rA + 64) * SS + cA;

    // row inverse sums (fixed-order, deterministic)
    float inv0, inv1;
    {
        const float4* p0 = (const float4*)(psum + (qrow0 + rA) * NTK);
        const float4* p1 = (const float4*)(psum + (qrow0 + rA + 64) * NTK);
        float s0 = 0.f, s1 = 0.f;
#pragma unroll
        for (int u = 0; u < 4; u++) {
            float4 a = p0[u]; s0 += ((a.x + a.y) + (a.z + a.w));
            float4 b = p1[u]; s1 += ((b.x + b.y) + (b.z + b.w));
        }
        inv0 = 1.0f / s0;
        inv1 = 1.0f / s1;
    }

    // V loader: 16x64 per stage, 2 float4 per thread
    const int vr0 = (t * 2)     >> 4, vc0 = ((t * 2)     & 15) * 4;
    const int vr1 = (t * 2 + 1) >> 4, vc1 = ((t * 2 + 1) & 15) * 4;

    float acc[4][4][4];
#pragma unroll
    for (int i = 0; i < 4; i++)
#pragma unroll
        for (int j = 0; j < 4; j++)
#pragma unroll
            for (int r = 0; r < 4; r++) acc[i][j][r] = 0.f;

    const int NST = (tq + 1) * 8;
    float4 pa[4], pv0, pv1;
    pa[0] = *(const float4*)(Aw0);     pa[1] = *(const float4*)(Aw0 + 4);
    pa[2] = *(const float4*)(Aw1);     pa[3] = *(const float4*)(Aw1 + 4);
    pv0 = *(const float4*)(Vb + (size_t)vr0 * DEPTH + vc0);
    pv1 = *(const float4*)(Vb + (size_t)vr1 * DEPTH + vc1);
    {
        float4 q0 = make_float4(pa[0].x * inv0, pa[0].y * inv0, pa[0].z * inv0, pa[0].w * inv0);
        float4 q1 = make_float4(pa[1].x * inv0, pa[1].y * inv0, pa[1].z * inv0, pa[1].w * inv0);
        float4 q2 = make_float4(pa[2].x * inv1, pa[2].y * inv1, pa[2].z * inv1, pa[2].w * inv1);
        float4 q3 = make_float4(pa[3].x * inv1, pa[3].y * inv1, pa[3].z * inv1, pa[3].w * inv1);
        *(uint4*)&As[0][rA][cA]          = tf4(q0, 1.f);
        *(uint4*)&As[0][rA][cA + 4]      = tf4(q1, 1.f);
        *(uint4*)&As[0][rA + 64][cA]     = tf4(q2, 1.f);
        *(uint4*)&As[0][rA + 64][cA + 4] = tf4(q3, 1.f);
        *(float4*)(Aw0)     = q0; *(float4*)(Aw0 + 4) = q1;   // writeback normalized
        *(float4*)(Aw1)     = q2; *(float4*)(Aw1 + 4) = q3;
        *(uint4*)&Vs[0][vr0][vc0] = tf4(pv0, 1.f);
        *(uint4*)&Vs[0][vr1][vc1] = tf4(pv1, 1.f);
    }
    __syncthreads();

    for (int s = 0; s < NST; s++) {
        const int off = (s + 1) * 16;
        if (s + 1 < NST) {
            pa[0] = *(const float4*)(Aw0 + off);  pa[1] = *(const float4*)(Aw0 + off + 4);
            pa[2] = *(const float4*)(Aw1 + off);  pa[3] = *(const float4*)(Aw1 + off + 4);
            pv0 = *(const float4*)(Vb + (size_t)(off + vr0) * DEPTH + vc0);
            pv1 = *(const float4*)(Vb + (size_t)(off + vr1) * DEPTH + vc1);
        }
        const int buf = s & 1;
#pragma unroll
        for (int ks = 0; ks < 16; ks += 8) {
            uint32_t a[4][4], b[4][2];
#pragma unroll
            for (int i = 0; i < 4; i++) {
                const int r = wm + i * 16;
                a[i][0] = As[buf][r + g][ks + tg];
                a[i][1] = As[buf][r + g + 8][ks + tg];
                a[i][2] = As[buf][r + g][ks + tg + 4];
                a[i][3] = As[buf][r + g + 8][ks + tg + 4];
            }
#pragma unroll
            for (int j = 0; j < 4; j++) {
                const int n = wn + j * 8;
                b[j][0] = Vs[buf][ks + tg][n + g];
                b[j][1] = Vs[buf][ks + tg + 4][n + g];
            }
#pragma unroll
            for (int i = 0; i < 4; i++)
#pragma unroll
                for (int j = 0; j < 4; j++)
                    mma_tf32(acc[i][j], a[i], b[j]);
        }
        if (s + 1 < NST) {
            const int nb = (s + 1) & 1;
            float4 q0 = make_float4(pa[0].x * inv0, pa[0].y * inv0, pa[0].z * inv0, pa[0].w * inv0);
            float4 q1 = make_float4(pa[1].x * inv0, pa[1].y * inv0, pa[1].z * inv0, pa[1].w * inv0);
            float4 q2 = make_float4(pa[2].x * inv1, pa[2].y * inv1, pa[2].z * inv1, pa[2].w * inv1);
            float4 q3 = make_float4(pa[3].x * inv1, pa[3].y * inv1, pa[3].z * inv1, pa[3].w * inv1);
            *(uint4*)&As[nb][rA][cA]          = tf4(q0, 1.f);
            *(uint4*)&As[nb][rA][cA + 4]      = tf4(q1, 1.f);
            *(uint4*)&As[nb][rA + 64][cA]     = tf4(q2, 1.f);
            *(uint4*)&As[nb][rA + 64][cA + 4] = tf4(q3, 1.f);
            *(float4*)(Aw0 + off)     = q0; *(float4*)(Aw0 + off + 4) = q1;
            *(float4*)(Aw1 + off)     = q2; *(float4*)(Aw1 + off + 4) = q3;
            *(uint4*)&Vs[nb][vr0][vc0] = tf4(pv0, 1.f);
            *(uint4*)&Vs[nb][vr1][vc1] = tf4(pv1, 1.f);
        }
        __syncthreads();
    }

#pragma unroll
    for (int i = 0; i < 4; i++) {
#pragma unroll
        for (int j = 0; j < 4; j++) {
            const int c = wn + j * 8 + 2 * tg;
#pragma unroll
            for (int half = 0; half < 2; half++) {
                const int q = tq * 128 + wm + i * 16 + g + half * 8;
                float* dst = &ctx[((size_t)bb * SS + q) * DD + h * DEPTH + c];
                dst[0] = acc[i][j][half * 2 + 0];
                dst[1] = acc[i][j][half * 2 + 1];
            }
        }
    }
}

// ---------------------------------------------------------------------------
extern "C" void kernel_launch(void* const* d_in, const int* in_sizes, int n_in,
                              void* d_out, int out_size)
{
    const float* q    = (const float*)d_in[0];
    const float* k    = (const float*)d_in[1];
    const float* v    = (const float*)d_in[2];
    // d_in[3] = mask (causal; applied analytically)
    const float* wq   = (const float*)d_in[4];
    const float* bq   = (const float*)d_in[5];
    const float* wk   = (const float*)d_in[6];
    const float* bk   = (const float*)d_in[7];
    const float* wv   = (const float*)d_in[8];
    const float* bv   = (const float*)d_in[9];
    const float* wo   = (const float*)d_in[10];
    const float* bo   = (const float*)d_in[11];
    float* out = (float*)d_out;

    float *gq, *gk, *gv, *gctx, *gattn, *gps;
    cudaGetSymbolAddress((void**)&gq,   g_q);
    cudaGetSymbolAddress((void**)&gk,   g_k);
    cudaGetSymbolAddress((void**)&gv,   g_v);
    cudaGetSymbolAddress((void**)&gctx, g_ctx);
    cudaGetSymbolAddress((void**)&gattn, g_attn_fb);
    cudaGetSymbolAddress((void**)&gps,  g_psum);

    const long long OUT_E = (long long)BB * SS * DD;
    const long long ATT_E = (long long)BB * HH * SS * SS;
    float* attn = ((long long)out_size >= OUT_E + ATT_E) ? (out + OUT_E) : gattn;

    const dim3 gproj(DD / 128, MTOT / 128);

    proj_tf32<<<gproj, 128>>>(q, wq, bq, gq, 1);
    proj_tf32<<<gproj, 128>>>(k, wk, bk, gk, 1);
    proj_tf32<<<gproj, 128>>>(v, wv, bv, gv, 1);

    attn_logits_exp<<<dim3(SS / 128, SS / 128, BB * HH), 256>>>(gq, gk, attn, gps);
    attn_ctx_tf32<<<dim3(SS / 128, BB * HH), 128>>>(attn, gv, gps, gctx);

    proj_tf32<<<gproj, 128>>>(gctx, wo, bo, out, 0);
}